// round 5
// baseline (speedup 1.0000x reference)
#include <cuda_runtime.h>
#include <stdint.h>

#define NC    32
#define KC    16
#define DSUB  128
#define INF   4096
#define OF    2048
#define MAXTOK 2048

typedef unsigned long long ull;

__device__ float         g_lut[NC * KC * OF];
__device__ unsigned char g_idx[MAXTOK * NC];

// ---- packed f32x2 helpers --------------------------------------------------
__device__ __forceinline__ ull pk2(float x, float y) {
    ull r; asm("mov.b64 %0, {%1,%2};" : "=l"(r) : "f"(x), "f"(y)); return r;
}
__device__ __forceinline__ void upk2(ull v, float& x, float& y) {
    asm("mov.b64 {%0,%1}, %2;" : "=f"(x), "=f"(y) : "l"(v));
}
__device__ __forceinline__ ull fma2(ull a, ull b, ull c) {
    ull d; asm("fma.rn.f32x2 %0, %1, %2, %3;" : "=l"(d) : "l"(a), "l"(b), "l"(c)); return d;
}
// load two packed f32x2 pairs straight from smem (no repack movs)
__device__ __forceinline__ void lds_v2u64(ull& a, ull& b, const float* p) {
    asm("{ .reg .u64 t; cvta.to.shared.u64 t, %2; ld.shared.v2.u64 {%0,%1}, [t]; }"
        : "=l"(a), "=l"(b) : "l"(p));
}

// ---------------------------------------------------------------------------
// K2 FIRST (independent of lut) so the ncu single-capture lands on a new kernel.
// idx — EXACT Round-1 version (known-good part of the 108.7us baseline).
// ---------------------------------------------------------------------------
__global__ void idx_kernel(const float* __restrict__ x,
                           const float* __restrict__ cent)
{
    extern __shared__ float sm[];
    float* xs  = sm;                      // 128 * 129
    float* cst = sm + 128 * 129;          // DSUB * KC (transposed)
    float* c2p = cst + DSUB * KC;         // 16 * 8 partials
    float* c2s = c2p + 16 * 8;            // 16

    const int c   = blockIdx.y;
    const int tb  = blockIdx.x * 128;
    const int tid = threadIdx.x;

    for (int i = tid; i < KC * DSUB; i += 128) {
        int k = i >> 7, d = i & 127;
        cst[d * KC + k] = cent[(c * KC + k) * DSUB + d];
    }
    for (int i = tid; i < 128 * DSUB / 4; i += 128) {
        int e   = i * 4;
        int row = e >> 7;
        int col = e & 127;
        float4 v = *(const float4*)&x[(size_t)(tb + row) * INF + c * DSUB + col];
        float* dst = &xs[row * 129 + col];
        dst[0] = v.x; dst[1] = v.y; dst[2] = v.z; dst[3] = v.w;
    }
    __syncthreads();

    {
        int k = tid >> 3, part = tid & 7;
        float s = 0.f;
        for (int d = part * 16; d < part * 16 + 16; d++) {
            float cv = cst[d * KC + k];
            s = fmaf(cv, cv, s);
        }
        c2p[k * 8 + part] = s;
    }
    __syncthreads();
    if (tid < 16) {
        float s = 0.f;
        for (int p = 0; p < 8; p++) s += c2p[tid * 8 + p];
        c2s[tid] = s;
    }
    __syncthreads();

    float acc[KC];
#pragma unroll
    for (int k = 0; k < KC; k++) acc[k] = 0.f;

    const float* xr = &xs[tid * 129];
#pragma unroll 2
    for (int d = 0; d < DSUB; d++) {
        float xv = xr[d];
#pragma unroll
        for (int k = 0; k < KC; k++)
            acc[k] = fmaf(xv, cst[d * KC + k], acc[k]);
    }

    float best = 1e30f, second = 1e30f;
    int bi = 0, si = 0;
#pragma unroll
    for (int k = 0; k < KC; k++) {
        float v = c2s[k] - 2.f * acc[k];
        if (v < best)        { second = best; si = bi; best = v; bi = k; }
        else if (v < second) { second = v; si = k; }
    }
    if (second - best < 1e-2f) {
        double vb = 0.0, vs = 0.0;
        for (int d = 0; d < DSUB; d++) {
            double xv = (double)xr[d];
            double cb = (double)cst[d * KC + bi];
            double cs = (double)cst[d * KC + si];
            vb += cb * (cb - 2.0 * xv);
            vs += cs * (cs - 2.0 * xv);
        }
        if (vs < vb || (vs == vb && si < bi)) bi = si;
    }
    g_idx[(size_t)(tb + tid) * NC + c] = (unsigned char)bi;
}

// ---------------------------------------------------------------------------
// K1: lut[c,k,o] = sum_d cent[c,k,d] * weight[c,d,o]
// grid (OF/128, NC), 512 threads. d split 4-ways inside the block:
// thread = (dq = tid>>7, col = tid&127); each thread: 32 d, two 16-deep LDG
// batches (64 B in flight/thread), k-pairs consumed as packed f32x2 via
// ld.shared.v2.u64 (zero repack movs). Smem reduction across d-quarters.
// ---------------------------------------------------------------------------
__global__ __launch_bounds__(512) void lut_kernel(const float* __restrict__ cent,
                                                  const float* __restrict__ weight)
{
    __shared__ float cst[DSUB * KC];        // cst[d][k], k consecutive (8 KB)
    __shared__ float red[3][KC][128];       // quarters 1..3 partials (24 KB)

    const int c   = blockIdx.y;
    const int tid = threadIdx.x;
    const int dq  = tid >> 7;               // d-quarter 0..3
    const int col = tid & 127;

    for (int i = tid; i < KC * DSUB; i += 512) {
        int k = i >> 7, d = i & 127;
        cst[d * KC + k] = cent[(c * KC + k) * DSUB + d];
    }
    __syncthreads();

    const int o = blockIdx.x * 128 + col;
    const float* wp = weight + (size_t)c * DSUB * OF + o + (size_t)(dq * 32) * OF;

    ull acc[8];
#pragma unroll
    for (int p = 0; p < 8; p++) acc[p] = 0ull;

#pragma unroll
    for (int half = 0; half < 2; half++) {
        float w[16];
#pragma unroll
        for (int i = 0; i < 16; i++) w[i] = wp[(size_t)(half * 16 + i) * OF];
#pragma unroll
        for (int i = 0; i < 16; i++) {
            ull wv = pk2(w[i], w[i]);
            const float* cp = &cst[(dq * 32 + half * 16 + i) * KC];
            ull a0, a1, a2, a3;
            lds_v2u64(a0, a1, cp);
            lds_v2u64(a2, a3, cp + 8);
            acc[0] = fma2(a0, wv, acc[0]);
            acc[1] = fma2(a1, wv, acc[1]);
            acc[2] = fma2(a2, wv, acc[2]);
            acc[3] = fma2(a3, wv, acc[3]);
            lds_v2u64(a0, a1, cp + 4);      // pairs (k8..k11) live at +8? no:
            // cst row is 16 floats: offsets 0..15. v2.u64 at +0 -> k0..3,
            // +4 floats -> k4..7, +8 -> k8..11, +12 -> k12..15.
            acc[4] = fma2(a0, wv, acc[4]);
            acc[5] = fma2(a1, wv, acc[5]);
            lds_v2u64(a2, a3, cp + 12);
            acc[6] = fma2(a2, wv, acc[6]);
            acc[7] = fma2(a3, wv, acc[7]);
        }
    }

    // NOTE ordering fix: acc[p] pairs must map to k = 2p. Above, loads at
    // offsets 0,+8,+4,+12 filled acc in order k(0..3), k(16..? ) — re-map:
    // acc[0]=k0k1, acc[1]=k2k3 (from +0); acc[2],acc[3] from +8 -> k8..11;
    // acc[4],acc[5] from +4 -> k4..7; acc[6],acc[7] from +12 -> k12..15.
    const int kmap[8] = {0, 1, 4, 5, 2, 3, 6, 7};   // acc slot -> k-pair index

    if (dq != 0) {
#pragma unroll
        for (int p = 0; p < 8; p++) {
            float v0, v1; upk2(acc[p], v0, v1);
            int kp = kmap[p];
            red[dq - 1][kp * 2 + 0][col] = v0;
            red[dq - 1][kp * 2 + 1][col] = v1;
        }
    }
    __syncthreads();
    if (dq == 0) {
#pragma unroll
        for (int p = 0; p < 8; p++) {
            float v0, v1; upk2(acc[p], v0, v1);
            int k0 = kmap[p] * 2, k1 = k0 + 1;
            v0 = v0 + red[0][k0][col] + red[1][k0][col] + red[2][k0][col];
            v1 = v1 + red[0][k1][col] + red[1][k1][col] + red[2][k1][col];
            g_lut[(size_t)(c * KC + k0) * OF + o] = v0;
            g_lut[(size_t)(c * KC + k1) * OF + o] = v1;
        }
    }
}

// ---------------------------------------------------------------------------
// K3: gather — EXACT Round-4 version (part of the 108.7us baseline).
// ---------------------------------------------------------------------------
__global__ __launch_bounds__(256) void gather_kernel(float* __restrict__ out,
                                                     const float* __restrict__ bias)
{
    extern __shared__ float sm[];
    float*         lut_s = sm;                                  // NC*KC*32 floats
    unsigned char* idx_s = (unsigned char*)(sm + NC * KC * 32); // 256*32 B

    const int ob  = blockIdx.x * 32;
    const int tb  = blockIdx.y * 256;
    const int tid = threadIdx.x;

    for (int i = tid; i < NC * KC * 32 / 4; i += 256) {
        int row = i >> 3;
        int col = (i & 7) * 4;
        float4 v = *(const float4*)&g_lut[(size_t)row * OF + ob + col];
        *(float4*)&lut_s[row * 32 + col] = v;
    }
    {
        const uint4* src = (const uint4*)&g_idx[(size_t)tb * NC];
        uint4* dst = (uint4*)idx_s;
        for (int i = tid; i < (256 * NC) / 16; i += 256) dst[i] = src[i];
    }
    __syncthreads();

    const int oi = tid & 31;
    const int tg = tid >> 5;
    const float bv = bias[ob + oi];

    for (int t = tg; t < 256; t += 8) {
        uint4 a = *(const uint4*)&idx_s[t * NC];
        uint4 b = *(const uint4*)&idx_s[t * NC + 16];
        unsigned int iw[8] = {a.x, a.y, a.z, a.w, b.x, b.y, b.z, b.w};
        float s0 = 0.f, s1 = 0.f;
#pragma unroll
        for (int c = 0; c < NC; c++) {
            unsigned int k = (iw[c >> 2] >> ((c & 3) * 8)) & 0xFFu;
            float v = lut_s[(c * KC + k) * 32 + oi];
            if (c & 1) s1 += v;
            else       s0 += v;
        }
        out[(size_t)(tb + t) * OF + ob + oi] = s0 + s1 + bv;
    }
}

// ---------------------------------------------------------------------------
extern "C" void kernel_launch(void* const* d_in, const int* in_sizes, int n_in,
                              void* d_out, int out_size)
{
    const float* x      = (const float*)d_in[0];
    const float* cent   = (const float*)d_in[1];
    const float* weight = (const float*)d_in[2];
    const float* bias   = (const float*)d_in[4];
    float* out = (float*)d_out;

    const int ntok = in_sizes[0] / INF;

    const int IDX_SMEM = (128 * 129 + DSUB * KC + 16 * 8 + 16) * (int)sizeof(float);
    const int G_SMEM   = NC * KC * 32 * (int)sizeof(float) + 256 * NC;

    cudaFuncSetAttribute(idx_kernel,    cudaFuncAttributeMaxDynamicSharedMemorySize, IDX_SMEM);
    cudaFuncSetAttribute(gather_kernel, cudaFuncAttributeMaxDynamicSharedMemorySize, G_SMEM);

    // idx first: independent of lut, and moves a different kernel under ncu's
    // single-capture window next profile.
    idx_kernel<<<dim3(ntok / 128, NC), 128, IDX_SMEM>>>(x, cent);
    lut_kernel<<<dim3(OF / 128, NC), 512>>>(cent, weight);
    gather_kernel<<<dim3(OF / 32, ntok / 256), 256, G_SMEM>>>(out, bias);
}

// round 6
// speedup vs baseline: 1.0619x; 1.0619x over previous
#include <cuda_runtime.h>
#include <stdint.h>

#define NC    32
#define KC    16
#define DSUB  128
#define INF   4096
#define OF    2048
#define MAXTOK 2048

typedef unsigned long long ull;

__device__ float         g_lut[NC * KC * OF];
__device__ unsigned char g_idx[MAXTOK * NC];

// ---- packed f32x2 helpers --------------------------------------------------
__device__ __forceinline__ ull pk2(float x, float y) {
    ull r; asm("mov.b64 %0, {%1,%2};" : "=l"(r) : "f"(x), "f"(y)); return r;
}
__device__ __forceinline__ void upk2(ull v, float& x, float& y) {
    asm("mov.b64 {%0,%1}, %2;" : "=f"(x), "=f"(y) : "l"(v));
}
__device__ __forceinline__ ull fma2(ull a, ull b, ull c) {
    ull d; asm("fma.rn.f32x2 %0, %1, %2, %3;" : "=l"(d) : "l"(a), "l"(b), "l"(c)); return d;
}
__device__ __forceinline__ void lds_v2u64(ull& a, ull& b, const float* p) {
    asm("{ .reg .u64 t; cvta.to.shared.u64 t, %2; ld.shared.v2.u64 {%0,%1}, [t]; }"
        : "=l"(a), "=l"(b) : "l"(p));
}

// smem layout for idx (floats)
#define XS_STRIDE 132                    // 528 B row: 16B-aligned, conflict-free
#define IDX_XS    (128 * XS_STRIDE)      // 16896
#define IDX_CST   (DSUB * KC)            // 2048
#define IDX_RED   (128 * 17)             // 2176
#define IDX_C2P   128
#define IDX_C2S   16
#define IDX_FLOATS (IDX_XS + IDX_CST + IDX_RED + IDX_C2P + IDX_C2S)

// ---------------------------------------------------------------------------
// K2: idx[token][c] = argmin_k ( c2[k] - 2 * <x_sub, cent_k> )
// v2: 256 threads, 128 tokens, d split in 2 halves/token (tid>>7).
// LDS.128 for both x (float4) and cst (broadcast) -> 4.25 LDS per 16 FFMA.
// Output indices invariant under reassociation: fp64 re-resolution of any
// near-tie (gap < 1e-2) makes the argmin exact.
// ---------------------------------------------------------------------------
__global__ __launch_bounds__(256) void idx_kernel(const float* __restrict__ x,
                                                  const float* __restrict__ cent)
{
    extern __shared__ float sm[];
    float* xs  = sm;                     // [128][XS_STRIDE]
    float* cst = sm + IDX_XS;            // [DSUB][KC]
    float* red = cst + IDX_CST;          // [128][17]
    float* c2p = red + IDX_RED;          // [16][8]
    float* c2s = c2p + IDX_C2P;          // [16]

    const int c   = blockIdx.y;
    const int tb  = blockIdx.x * 128;
    const int tid = threadIdx.x;

    for (int i = tid; i < KC * DSUB; i += 256) {
        int k = i >> 7, d = i & 127;
        cst[d * KC + k] = cent[(c * KC + k) * DSUB + d];
    }
    // stage x tile: 128 tokens x 128 dims, coalesced float4
    for (int i = tid; i < 128 * DSUB / 4; i += 256) {
        int e = i * 4, row = e >> 7, col = e & 127;
        float4 v = *(const float4*)&x[(size_t)(tb + row) * INF + c * DSUB + col];
        *(float4*)&xs[row * XS_STRIDE + col] = v;
    }
    __syncthreads();

    if (tid < 128) {
        int k = tid >> 3, part = tid & 7;
        float s = 0.f;
        for (int d = part * 16; d < part * 16 + 16; d++) {
            float cv = cst[d * KC + k];
            s = fmaf(cv, cv, s);
        }
        c2p[k * 8 + part] = s;
    }
    __syncthreads();
    if (tid < 16) {
        float s = 0.f;
        for (int p = 0; p < 8; p++) s += c2p[tid * 8 + p];
        c2s[tid] = s;
    }
    __syncthreads();

    const int token = tid & 127;
    const int half  = tid >> 7;
    const int dbase = half * 64;

    float acc[KC];
#pragma unroll
    for (int k = 0; k < KC; k++) acc[k] = 0.f;

    const float* xr = &xs[token * XS_STRIDE];
    for (int d0 = dbase; d0 < dbase + 64; d0 += 4) {
        float4 xq = *(const float4*)&xr[d0];
        float xv4[4] = {xq.x, xq.y, xq.z, xq.w};
#pragma unroll
        for (int j = 0; j < 4; j++) {
            float xv = xv4[j];
            const float4* cp = (const float4*)&cst[(d0 + j) * KC];
            float4 c0 = cp[0], c1 = cp[1], c2v = cp[2], c3 = cp[3];
            acc[0]  = fmaf(xv, c0.x, acc[0]);   acc[1]  = fmaf(xv, c0.y, acc[1]);
            acc[2]  = fmaf(xv, c0.z, acc[2]);   acc[3]  = fmaf(xv, c0.w, acc[3]);
            acc[4]  = fmaf(xv, c1.x, acc[4]);   acc[5]  = fmaf(xv, c1.y, acc[5]);
            acc[6]  = fmaf(xv, c1.z, acc[6]);   acc[7]  = fmaf(xv, c1.w, acc[7]);
            acc[8]  = fmaf(xv, c2v.x, acc[8]);  acc[9]  = fmaf(xv, c2v.y, acc[9]);
            acc[10] = fmaf(xv, c2v.z, acc[10]); acc[11] = fmaf(xv, c2v.w, acc[11]);
            acc[12] = fmaf(xv, c3.x, acc[12]);  acc[13] = fmaf(xv, c3.y, acc[13]);
            acc[14] = fmaf(xv, c3.z, acc[14]);  acc[15] = fmaf(xv, c3.w, acc[15]);
        }
    }

    if (half == 1) {
#pragma unroll
        for (int k = 0; k < KC; k++) red[token * 17 + k] = acc[k];
    }
    __syncthreads();
    if (half == 0) {
        float best = 1e30f, second = 1e30f;
        int bi = 0, si = 0;
#pragma unroll
        for (int k = 0; k < KC; k++) {
            float dot = acc[k] + red[token * 17 + k];
            float v = c2s[k] - 2.f * dot;
            if (v < best)        { second = best; si = bi; best = v; bi = k; }
            else if (v < second) { second = v; si = k; }
        }
        if (second - best < 1e-2f) {
            double vb = 0.0, vs = 0.0;
            for (int d = 0; d < DSUB; d++) {
                double xv = (double)xr[d];
                double cb = (double)cst[d * KC + bi];
                double cs = (double)cst[d * KC + si];
                vb += cb * (cb - 2.0 * xv);
                vs += cs * (cs - 2.0 * xv);
            }
            if (vs < vb || (vs == vb && si < bi)) bi = si;
        }
        g_idx[(size_t)(tb + token) * NC + c] = (unsigned char)bi;
    }
}

// ---------------------------------------------------------------------------
// K1: lut — EXACT Round-5 version (unchanged; isolate the idx experiment).
// ---------------------------------------------------------------------------
__global__ __launch_bounds__(512) void lut_kernel(const float* __restrict__ cent,
                                                  const float* __restrict__ weight)
{
    __shared__ float cst[DSUB * KC];
    __shared__ float red[3][KC][128];

    const int c   = blockIdx.y;
    const int tid = threadIdx.x;
    const int dq  = tid >> 7;
    const int col = tid & 127;

    for (int i = tid; i < KC * DSUB; i += 512) {
        int k = i >> 7, d = i & 127;
        cst[d * KC + k] = cent[(c * KC + k) * DSUB + d];
    }
    __syncthreads();

    const int o = blockIdx.x * 128 + col;
    const float* wp = weight + (size_t)c * DSUB * OF + o + (size_t)(dq * 32) * OF;

    ull acc[8];
#pragma unroll
    for (int p = 0; p < 8; p++) acc[p] = 0ull;

#pragma unroll
    for (int half = 0; half < 2; half++) {
        float w[16];
#pragma unroll
        for (int i = 0; i < 16; i++) w[i] = wp[(size_t)(half * 16 + i) * OF];
#pragma unroll
        for (int i = 0; i < 16; i++) {
            ull wv = pk2(w[i], w[i]);
            const float* cp = &cst[(dq * 32 + half * 16 + i) * KC];
            ull a0, a1, a2, a3;
            lds_v2u64(a0, a1, cp);
            lds_v2u64(a2, a3, cp + 8);
            acc[0] = fma2(a0, wv, acc[0]);
            acc[1] = fma2(a1, wv, acc[1]);
            acc[2] = fma2(a2, wv, acc[2]);
            acc[3] = fma2(a3, wv, acc[3]);
            lds_v2u64(a0, a1, cp + 4);
            acc[4] = fma2(a0, wv, acc[4]);
            acc[5] = fma2(a1, wv, acc[5]);
            lds_v2u64(a2, a3, cp + 12);
            acc[6] = fma2(a2, wv, acc[6]);
            acc[7] = fma2(a3, wv, acc[7]);
        }
    }

    const int kmap[8] = {0, 1, 4, 5, 2, 3, 6, 7};

    if (dq != 0) {
#pragma unroll
        for (int p = 0; p < 8; p++) {
            float v0, v1; upk2(acc[p], v0, v1);
            int kp = kmap[p];
            red[dq - 1][kp * 2 + 0][col] = v0;
            red[dq - 1][kp * 2 + 1][col] = v1;
        }
    }
    __syncthreads();
    if (dq == 0) {
#pragma unroll
        for (int p = 0; p < 8; p++) {
            float v0, v1; upk2(acc[p], v0, v1);
            int k0 = kmap[p] * 2, k1 = k0 + 1;
            v0 = v0 + red[0][k0][col] + red[1][k0][col] + red[2][k0][col];
            v1 = v1 + red[0][k1][col] + red[1][k1][col] + red[2][k1][col];
            g_lut[(size_t)(c * KC + k0) * OF + o] = v0;
            g_lut[(size_t)(c * KC + k1) * OF + o] = v1;
        }
    }
}

// ---------------------------------------------------------------------------
// K3: gather — EXACT Round-4 version (unchanged).
// ---------------------------------------------------------------------------
__global__ __launch_bounds__(256) void gather_kernel(float* __restrict__ out,
                                                     const float* __restrict__ bias)
{
    extern __shared__ float sm[];
    float*         lut_s = sm;
    unsigned char* idx_s = (unsigned char*)(sm + NC * KC * 32);

    const int ob  = blockIdx.x * 32;
    const int tb  = blockIdx.y * 256;
    const int tid = threadIdx.x;

    for (int i = tid; i < NC * KC * 32 / 4; i += 256) {
        int row = i >> 3;
        int col = (i & 7) * 4;
        float4 v = *(const float4*)&g_lut[(size_t)row * OF + ob + col];
        *(float4*)&lut_s[row * 32 + col] = v;
    }
    {
        const uint4* src = (const uint4*)&g_idx[(size_t)tb * NC];
        uint4* dst = (uint4*)idx_s;
        for (int i = tid; i < (256 * NC) / 16; i += 256) dst[i] = src[i];
    }
    __syncthreads();

    const int oi = tid & 31;
    const int tg = tid >> 5;
    const float bv = bias[ob + oi];

    for (int t = tg; t < 256; t += 8) {
        uint4 a = *(const uint4*)&idx_s[t * NC];
        uint4 b = *(const uint4*)&idx_s[t * NC + 16];
        unsigned int iw[8] = {a.x, a.y, a.z, a.w, b.x, b.y, b.z, b.w};
        float s0 = 0.f, s1 = 0.f;
#pragma unroll
        for (int c = 0; c < NC; c++) {
            unsigned int k = (iw[c >> 2] >> ((c & 3) * 8)) & 0xFFu;
            float v = lut_s[(c * KC + k) * 32 + oi];
            if (c & 1) s1 += v;
            else       s0 += v;
        }
        out[(size_t)(tb + t) * OF + ob + oi] = s0 + s1 + bv;
    }
}

// ---------------------------------------------------------------------------
extern "C" void kernel_launch(void* const* d_in, const int* in_sizes, int n_in,
                              void* d_out, int out_size)
{
    const float* x      = (const float*)d_in[0];
    const float* cent   = (const float*)d_in[1];
    const float* weight = (const float*)d_in[2];
    const float* bias   = (const float*)d_in[4];
    float* out = (float*)d_out;

    const int ntok = in_sizes[0] / INF;

    const int IDX_SMEM = IDX_FLOATS * (int)sizeof(float);      // ~85 KB -> 2 CTAs/SM
    const int G_SMEM   = NC * KC * 32 * (int)sizeof(float) + 256 * NC;

    cudaFuncSetAttribute(idx_kernel,    cudaFuncAttributeMaxDynamicSharedMemorySize, IDX_SMEM);
    cudaFuncSetAttribute(gather_kernel, cudaFuncAttributeMaxDynamicSharedMemorySize, G_SMEM);

    idx_kernel<<<dim3(ntok / 128, NC), 256, IDX_SMEM>>>(x, cent);
    lut_kernel<<<dim3(OF / 128, NC), 512>>>(cent, weight);
    gather_kernel<<<dim3(OF / 32, ntok / 256), 256, G_SMEM>>>(out, bias);
}

// round 7
// speedup vs baseline: 1.1982x; 1.1284x over previous
#include <cuda_runtime.h>
#include <stdint.h>

#define NC    32
#define KC    16
#define DSUB  128
#define INF   4096
#define OF    2048
#define MAXTOK 2048

typedef unsigned long long ull;

__device__ float         g_lut[NC * KC * OF];
__device__ unsigned char g_idx[MAXTOK * NC];

// ---- packed f32x2 helpers --------------------------------------------------
__device__ __forceinline__ ull pk2(float x, float y) {
    ull r; asm("mov.b64 %0, {%1,%2};" : "=l"(r) : "f"(x), "f"(y)); return r;
}
__device__ __forceinline__ void upk2(ull v, float& x, float& y) {
    asm("mov.b64 {%0,%1}, %2;" : "=f"(x), "=f"(y) : "l"(v));
}
__device__ __forceinline__ ull fma2(ull a, ull b, ull c) {
    ull d; asm("fma.rn.f32x2 %0, %1, %2, %3;" : "=l"(d) : "l"(a), "l"(b), "l"(c)); return d;
}
__device__ __forceinline__ void lds_v2u64(ull& a, ull& b, const float* p) {
    asm("{ .reg .u64 t; cvta.to.shared.u64 t, %2; ld.shared.v2.u64 {%0,%1}, [t]; }"
        : "=l"(a), "=l"(b) : "l"(p));
}

// smem layout for idx (floats)
#define XS_STRIDE 132
#define IDX_XS    (128 * XS_STRIDE)
#define IDX_CST   (DSUB * KC)
#define IDX_RED   (128 * 17)
#define IDX_C2P   128
#define IDX_C2S   16
#define IDX_FLOATS (IDX_XS + IDX_CST + IDX_RED + IDX_C2P + IDX_C2S)

// ---------------------------------------------------------------------------
// K2: idx[token][c] = argmin_k ( c2[k] - 2 * <x_sub, cent_k> )
// v3: x staging with MLP — two 8-deep batches of independent LDG.128 before
// any STS, so each thread holds 128 B in flight (-> ~64 KB/SM, streams at
// HBM rate instead of 1-load-deep latency serialization).
// Everything after staging is byte-identical to R6 (same bits out).
// ---------------------------------------------------------------------------
__global__ __launch_bounds__(256) void idx_kernel(const float* __restrict__ x,
                                                  const float* __restrict__ cent)
{
    extern __shared__ float sm[];
    float* xs  = sm;                     // [128][XS_STRIDE]
    float* cst = sm + IDX_XS;            // [DSUB][KC]
    float* red = cst + IDX_CST;          // [128][17]
    float* c2p = red + IDX_RED;          // [16][8]
    float* c2s = c2p + IDX_C2P;          // [16]

    const int c   = blockIdx.y;
    const int tb  = blockIdx.x * 128;
    const int tid = threadIdx.x;

    // stage x tile FIRST (get the DRAM traffic in flight early):
    // 4096 float4 vecs; thread handles vec ids tid + j*256, j = 0..15,
    // in two 8-deep LDG batches followed by the 8 STS.
#pragma unroll
    for (int b = 0; b < 2; b++) {
        float4 buf[8];
#pragma unroll
        for (int j = 0; j < 8; j++) {
            int i   = tid + (b * 8 + j) * 256;
            int row = i >> 5;            // 32 vecs per row
            int col = (i & 31) * 4;
            buf[j] = *(const float4*)&x[(size_t)(tb + row) * INF + c * DSUB + col];
        }
#pragma unroll
        for (int j = 0; j < 8; j++) {
            int i   = tid + (b * 8 + j) * 256;
            int row = i >> 5;
            int col = (i & 31) * 4;
            *(float4*)&xs[row * XS_STRIDE + col] = buf[j];
        }
    }
    // centroid transpose (small: 8 KB, coalesced over d)
    for (int i = tid; i < KC * DSUB; i += 256) {
        int k = i >> 7, d = i & 127;
        cst[d * KC + k] = cent[(c * KC + k) * DSUB + d];
    }
    __syncthreads();

    if (tid < 128) {
        int k = tid >> 3, part = tid & 7;
        float s = 0.f;
        for (int d = part * 16; d < part * 16 + 16; d++) {
            float cv = cst[d * KC + k];
            s = fmaf(cv, cv, s);
        }
        c2p[k * 8 + part] = s;
    }
    __syncthreads();
    if (tid < 16) {
        float s = 0.f;
        for (int p = 0; p < 8; p++) s += c2p[tid * 8 + p];
        c2s[tid] = s;
    }
    __syncthreads();

    const int token = tid & 127;
    const int half  = tid >> 7;
    const int dbase = half * 64;

    float acc[KC];
#pragma unroll
    for (int k = 0; k < KC; k++) acc[k] = 0.f;

    const float* xr = &xs[token * XS_STRIDE];
    for (int d0 = dbase; d0 < dbase + 64; d0 += 4) {
        float4 xq = *(const float4*)&xr[d0];
        float xv4[4] = {xq.x, xq.y, xq.z, xq.w};
#pragma unroll
        for (int j = 0; j < 4; j++) {
            float xv = xv4[j];
            const float4* cp = (const float4*)&cst[(d0 + j) * KC];
            float4 c0 = cp[0], c1 = cp[1], c2v = cp[2], c3 = cp[3];
            acc[0]  = fmaf(xv, c0.x, acc[0]);   acc[1]  = fmaf(xv, c0.y, acc[1]);
            acc[2]  = fmaf(xv, c0.z, acc[2]);   acc[3]  = fmaf(xv, c0.w, acc[3]);
            acc[4]  = fmaf(xv, c1.x, acc[4]);   acc[5]  = fmaf(xv, c1.y, acc[5]);
            acc[6]  = fmaf(xv, c1.z, acc[6]);   acc[7]  = fmaf(xv, c1.w, acc[7]);
            acc[8]  = fmaf(xv, c2v.x, acc[8]);  acc[9]  = fmaf(xv, c2v.y, acc[9]);
            acc[10] = fmaf(xv, c2v.z, acc[10]); acc[11] = fmaf(xv, c2v.w, acc[11]);
            acc[12] = fmaf(xv, c3.x, acc[12]);  acc[13] = fmaf(xv, c3.y, acc[13]);
            acc[14] = fmaf(xv, c3.z, acc[14]);  acc[15] = fmaf(xv, c3.w, acc[15]);
        }
    }

    if (half == 1) {
#pragma unroll
        for (int k = 0; k < KC; k++) red[token * 17 + k] = acc[k];
    }
    __syncthreads();
    if (half == 0) {
        float best = 1e30f, second = 1e30f;
        int bi = 0, si = 0;
#pragma unroll
        for (int k = 0; k < KC; k++) {
            float dot = acc[k] + red[token * 17 + k];
            float v = c2s[k] - 2.f * dot;
            if (v < best)        { second = best; si = bi; best = v; bi = k; }
            else if (v < second) { second = v; si = k; }
        }
        // fp32 error on v is ~3e-5; any gap > 1e-3 is already decided
        // correctly in fp32, so 1e-3 trigger keeps the argmin exact while
        // entering the fp64 path ~10x less often.
        if (second - best < 1e-3f) {
            double vb = 0.0, vs = 0.0;
            for (int d = 0; d < DSUB; d++) {
                double xv = (double)xr[d];
                double cb = (double)cst[d * KC + bi];
                double cs = (double)cst[d * KC + si];
                vb += cb * (cb - 2.0 * xv);
                vs += cs * (cs - 2.0 * xv);
            }
            if (vs < vb || (vs == vb && si < bi)) bi = si;
        }
        g_idx[(size_t)(tb + token) * NC + c] = (unsigned char)bi;
    }
}

// ---------------------------------------------------------------------------
// K1: lut — EXACT Round-5 version (unchanged).
// ---------------------------------------------------------------------------
__global__ __launch_bounds__(512) void lut_kernel(const float* __restrict__ cent,
                                                  const float* __restrict__ weight)
{
    __shared__ float cst[DSUB * KC];
    __shared__ float red[3][KC][128];

    const int c   = blockIdx.y;
    const int tid = threadIdx.x;
    const int dq  = tid >> 7;
    const int col = tid & 127;

    for (int i = tid; i < KC * DSUB; i += 512) {
        int k = i >> 7, d = i & 127;
        cst[d * KC + k] = cent[(c * KC + k) * DSUB + d];
    }
    __syncthreads();

    const int o = blockIdx.x * 128 + col;
    const float* wp = weight + (size_t)c * DSUB * OF + o + (size_t)(dq * 32) * OF;

    ull acc[8];
#pragma unroll
    for (int p = 0; p < 8; p++) acc[p] = 0ull;

#pragma unroll
    for (int half = 0; half < 2; half++) {
        float w[16];
#pragma unroll
        for (int i = 0; i < 16; i++) w[i] = wp[(size_t)(half * 16 + i) * OF];
#pragma unroll
        for (int i = 0; i < 16; i++) {
            ull wv = pk2(w[i], w[i]);
            const float* cp = &cst[(dq * 32 + half * 16 + i) * KC];
            ull a0, a1, a2, a3;
            lds_v2u64(a0, a1, cp);
            lds_v2u64(a2, a3, cp + 8);
            acc[0] = fma2(a0, wv, acc[0]);
            acc[1] = fma2(a1, wv, acc[1]);
            acc[2] = fma2(a2, wv, acc[2]);
            acc[3] = fma2(a3, wv, acc[3]);
            lds_v2u64(a0, a1, cp + 4);
            acc[4] = fma2(a0, wv, acc[4]);
            acc[5] = fma2(a1, wv, acc[5]);
            lds_v2u64(a2, a3, cp + 12);
            acc[6] = fma2(a2, wv, acc[6]);
            acc[7] = fma2(a3, wv, acc[7]);
        }
    }

    const int kmap[8] = {0, 1, 4, 5, 2, 3, 6, 7};

    if (dq != 0) {
#pragma unroll
        for (int p = 0; p < 8; p++) {
            float v0, v1; upk2(acc[p], v0, v1);
            int kp = kmap[p];
            red[dq - 1][kp * 2 + 0][col] = v0;
            red[dq - 1][kp * 2 + 1][col] = v1;
        }
    }
    __syncthreads();
    if (dq == 0) {
#pragma unroll
        for (int p = 0; p < 8; p++) {
            float v0, v1; upk2(acc[p], v0, v1);
            int k0 = kmap[p] * 2, k1 = k0 + 1;
            v0 = v0 + red[0][k0][col] + red[1][k0][col] + red[2][k0][col];
            v1 = v1 + red[0][k1][col] + red[1][k1][col] + red[2][k1][col];
            g_lut[(size_t)(c * KC + k0) * OF + o] = v0;
            g_lut[(size_t)(c * KC + k1) * OF + o] = v1;
        }
    }
}

// ---------------------------------------------------------------------------
// K3: gather — EXACT Round-4 version (unchanged).
// ---------------------------------------------------------------------------
__global__ __launch_bounds__(256) void gather_kernel(float* __restrict__ out,
                                                     const float* __restrict__ bias)
{
    extern __shared__ float sm[];
    float*         lut_s = sm;
    unsigned char* idx_s = (unsigned char*)(sm + NC * KC * 32);

    const int ob  = blockIdx.x * 32;
    const int tb  = blockIdx.y * 256;
    const int tid = threadIdx.x;

    for (int i = tid; i < NC * KC * 32 / 4; i += 256) {
        int row = i >> 3;
        int col = (i & 7) * 4;
        float4 v = *(const float4*)&g_lut[(size_t)row * OF + ob + col];
        *(float4*)&lut_s[row * 32 + col] = v;
    }
    {
        const uint4* src = (const uint4*)&g_idx[(size_t)tb * NC];
        uint4* dst = (uint4*)idx_s;
        for (int i = tid; i < (256 * NC) / 16; i += 256) dst[i] = src[i];
    }
    __syncthreads();

    const int oi = tid & 31;
    const int tg = tid >> 5;
    const float bv = bias[ob + oi];

    for (int t = tg; t < 256; t += 8) {
        uint4 a = *(const uint4*)&idx_s[t * NC];
        uint4 b = *(const uint4*)&idx_s[t * NC + 16];
        unsigned int iw[8] = {a.x, a.y, a.z, a.w, b.x, b.y, b.z, b.w};
        float s0 = 0.f, s1 = 0.f;
#pragma unroll
        for (int c = 0; c < NC; c++) {
            unsigned int k = (iw[c >> 2] >> ((c & 3) * 8)) & 0xFFu;
            float v = lut_s[(c * KC + k) * 32 + oi];
            if (c & 1) s1 += v;
            else       s0 += v;
        }
        out[(size_t)(tb + t) * OF + ob + oi] = s0 + s1 + bv;
    }
}

// ---------------------------------------------------------------------------
extern "C" void kernel_launch(void* const* d_in, const int* in_sizes, int n_in,
                              void* d_out, int out_size)
{
    const float* x      = (const float*)d_in[0];
    const float* cent   = (const float*)d_in[1];
    const float* weight = (const float*)d_in[2];
    const float* bias   = (const float*)d_in[4];
    float* out = (float*)d_out;

    const int ntok = in_sizes[0] / INF;

    const int IDX_SMEM = IDX_FLOATS * (int)sizeof(float);
    const int G_SMEM   = NC * KC * 32 * (int)sizeof(float) + 256 * NC;

    cudaFuncSetAttribute(idx_kernel,    cudaFuncAttributeMaxDynamicSharedMemorySize, IDX_SMEM);
    cudaFuncSetAttribute(gather_kernel, cudaFuncAttributeMaxDynamicSharedMemorySize, G_SMEM);

    idx_kernel<<<dim3(ntok / 128, NC), 256, IDX_SMEM>>>(x, cent);
    lut_kernel<<<dim3(OF / 128, NC), 512>>>(cent, weight);
    gather_kernel<<<dim3(OF / 32, ntok / 256), 256, G_SMEM>>>(out, bias);
}